// round 13
// baseline (speedup 1.0000x reference)
#include <cuda_runtime.h>
#include <cstdint>

// ViewControlPreprocessor (non-causal path), GB300 sm_103a.
//   hidden_states: (1536, 21, 3072) f32
//   view_control_condition: (1, 81, 16) f32  -> 5KB L1/L2-resident table
//   output: (1536, 21, 3200) f32
//
//   out[r, :3072]            = hidden[r, :]
//   out[r, 3072 + p*16 + c]  = vcc[max(4*(r%21)+p-8, 0), c],  p in [0,8)
//
// R13: hint-isolation experiment. Identical to the established optimum
// (256thr / UNROLL=4 / predicate-free float4 swarm, 112.1-113.6us kernel
// over 4 runs @ ~6.7TB/s) EXCEPT all cache hints removed: default-policy
// loads and stores. Tests whether L2 write-allocate buffering presents
// longer write bursts to the HBM controller (attacking the R/W-turnaround
// loss that is the only remaining gap to spec).

static constexpr int T_Q     = 21;
static constexpr int ROWS    = 1536 * 21;          // 32256
static constexpr int HID_F4  = 3072 / 4;           // 768 float4 per row (hidden)
static constexpr int ROW_F4  = 800;                // float4 per output row
static constexpr int PAD_T   = 8;
static constexpr long long TOTAL_F4 = (long long)ROWS * ROW_F4;  // 25,804,800
static constexpr int THREADS = 256;
static constexpr int UNROLL  = 4;
// 25,804,800 / (256*4) = 25200 exactly -> predicate-free grid.
static constexpr int BLOCKS  = (int)(TOTAL_F4 / (THREADS * UNROLL));

__device__ __forceinline__ float4 fetch_one(const float4* __restrict__ hidden,
                                            const float4* __restrict__ vcc,
                                            int i)
{
    int row  = i / ROW_F4;          // compile-time-constant divide -> IMAD magic
    int col4 = i - row * ROW_F4;

    if (col4 < HID_F4) {
        // hidden_idx = row*768 + col4 = i - 32*row
        return hidden[i - 32 * row];            // default-policy load
    } else {
        int c4 = col4 - HID_F4;      // 0..31
        int p  = c4 >> 2;            // PAD_T slot (0..7)
        int q  = c4 & 3;             // float4 within 16-float channel row
        int t  = row % T_Q;          // compile-time-constant mod
        int j  = 4 * t + p;          // padded index 0..88
        int src = (j < PAD_T) ? 0 : (j - PAD_T);
        return __ldg(&vcc[src * 4 + q]);   // 5KB table, L1-resident
    }
}

__global__ void __launch_bounds__(THREADS)
vcp_fuse_kernel(const float4* __restrict__ hidden,
                const float4* __restrict__ vcc,
                float4* __restrict__ out)
{
    // Block covers 1024 consecutive float4 (16KB dst span); each 256-thread
    // sweep is a contiguous, perfectly coalesced 4KB span. Warp spans never
    // straddle the hidden/tail boundary (768 and 800 are multiples of 32)
    // -> zero intra-warp divergence.
    int base = blockIdx.x * (THREADS * UNROLL) + threadIdx.x;

    float4 v[UNROLL];
    // Batch all loads first (per-thread MLP = 4), then all stores.
    #pragma unroll
    for (int u = 0; u < UNROLL; u++) {
        v[u] = fetch_one(hidden, vcc, base + u * THREADS);
    }
    #pragma unroll
    for (int u = 0; u < UNROLL; u++) {
        out[base + u * THREADS] = v[u];         // default-policy store
    }
}

extern "C" void kernel_launch(void* const* d_in, const int* in_sizes, int n_in,
                              void* d_out, int out_size)
{
    const float4* hidden = (const float4*)d_in[0];
    const float4* vcc    = (const float4*)d_in[1];
    float4* out = (float4*)d_out;

    vcp_fuse_kernel<<<BLOCKS, THREADS>>>(hidden, vcc, out);
}

// round 14
// speedup vs baseline: 1.0011x; 1.0011x over previous
#include <cuda_runtime.h>
#include <cstdint>

// ViewControlPreprocessor (non-causal path), GB300 sm_103a.  FINAL.
//   hidden_states: (1536, 21, 3072) f32
//   view_control_condition: (1, 81, 16) f32  -> 5KB L1-resident table
//   output: (1536, 21, 3200) f32
//
//   out[r, :3072]            = hidden[r, :]
//   out[r, 3072 + p*16 + c]  = vcc[max(4*(r%21)+p-8, 0), c],  p in [0,8)
//
// Roofline: compulsory 396MB read + 413MB write. Measured GB300 mixed-R/W
// plateau 6.64-6.73 TB/s (83-85% of 8TB/s spec) over 5 runs of this config;
// run-to-run noise +/-1.5us kernel. Complete lever sweep (kernel us):
//   256thr/U4 float4 predicate-free .cs: 112.1-113.6  <- THIS (canonical)
//   same, default cache policy:          112.9        (hints immaterial)
//   256thr/U8 float4:                    113.1-113.4  (MLP immaterial)
//   128thr/U4 float4:                    113.6        (2KB sweeps slightly worse)
//   256thr/U2 v8.f32 256-bit ops:        113.8        (fewer wavefronts ->
//                                         worse DRAM request interleave)
//   persistent 888-block grid:           120.8        (tail starvation)
//   copy-engine memcpy2D:                ~390         (row-segmented CE path)
// Residual ~15% vs spec is HBM controller R/W turnaround on a bidirectional
// stream — invariant under MLP, occupancy, access width, cache policy, and
// transport path. Not addressable from SASS. Hardware roofline reached.

static constexpr int T_Q     = 21;
static constexpr int ROWS    = 1536 * 21;          // 32256
static constexpr int HID_F4  = 3072 / 4;           // 768 float4 per row (hidden)
static constexpr int ROW_F4  = 800;                // float4 per output row
static constexpr int PAD_T   = 8;
static constexpr long long TOTAL_F4 = (long long)ROWS * ROW_F4;  // 25,804,800
static constexpr int THREADS = 256;
static constexpr int UNROLL  = 4;
// 25,804,800 / (256*4) = 25200 exactly -> predicate-free grid.
static constexpr int BLOCKS  = (int)(TOTAL_F4 / (THREADS * UNROLL));

__device__ __forceinline__ float4 fetch_one(const float4* __restrict__ hidden,
                                            const float4* __restrict__ vcc,
                                            int i)
{
    int row  = i / ROW_F4;          // compile-time-constant divide -> IMAD magic
    int col4 = i - row * ROW_F4;

    if (col4 < HID_F4) {
        // hidden_idx = row*768 + col4 = i - 32*row
        return __ldcs(&hidden[i - 32 * row]);   // streaming: read exactly once
    } else {
        int c4 = col4 - HID_F4;      // 0..31
        int p  = c4 >> 2;            // PAD_T slot (0..7)
        int q  = c4 & 3;             // float4 within 16-float channel row
        int t  = row % T_Q;          // compile-time-constant mod
        int j  = 4 * t + p;          // padded index 0..88
        int src = (j < PAD_T) ? 0 : (j - PAD_T);
        return __ldg(&vcc[src * 4 + q]);   // 5KB table, L1-resident
    }
}

__global__ void __launch_bounds__(THREADS)
vcp_fuse_kernel(const float4* __restrict__ hidden,
                const float4* __restrict__ vcc,
                float4* __restrict__ out)
{
    // Block covers 1024 consecutive float4 (16KB dst span); each 256-thread
    // sweep is a contiguous, perfectly coalesced 4KB span. Warp spans never
    // straddle the hidden/tail boundary (768 and 800 are multiples of 32)
    // -> zero intra-warp divergence.
    int base = blockIdx.x * (THREADS * UNROLL) + threadIdx.x;

    float4 v[UNROLL];
    // Batch all loads first (per-thread MLP = 4), then all stores.
    #pragma unroll
    for (int u = 0; u < UNROLL; u++) {
        v[u] = fetch_one(hidden, vcc, base + u * THREADS);
    }
    #pragma unroll
    for (int u = 0; u < UNROLL; u++) {
        __stcs(&out[base + u * THREADS], v[u]);   // streaming store: never re-read
    }
}

extern "C" void kernel_launch(void* const* d_in, const int* in_sizes, int n_in,
                              void* d_out, int out_size)
{
    const float4* hidden = (const float4*)d_in[0];
    const float4* vcc    = (const float4*)d_in[1];
    float4* out = (float4*)d_out;

    vcp_fuse_kernel<<<BLOCKS, THREADS>>>(hidden, vcc, out);
}

// round 15
// speedup vs baseline: 1.0126x; 1.0115x over previous
#include <cuda_runtime.h>
#include <cstdint>

// ViewControlPreprocessor (non-causal path), GB300 sm_103a.  FINAL (held).
//   hidden_states: (1536, 21, 3072) f32
//   view_control_condition: (1, 81, 16) f32  -> 5KB L1-resident table
//   output: (1536, 21, 3200) f32
//
//   out[r, :3072]            = hidden[r, :]
//   out[r, 3072 + p*16 + c]  = vcc[max(4*(r%21)+p-8, 0), c],  p in [0,8)
//
// Roofline: compulsory 396MB read + 413MB write. Measured GB300 mixed-R/W
// plateau 6.62-6.73 TB/s (83-85% of 8TB/s spec) over SIX runs of this exact
// config (kernel 112.1-114.1us; wall 119.1-120.8us incl. ~7us fixed harness
// replay overhead). Complete lever sweep, all isolated (kernel us):
//   256thr/U4 float4 predicate-free .cs: 112.1-114.1  <- THIS (canonical)
//   same, default cache policy:          112.9        (hints immaterial)
//   256thr/U8 float4:                    113.1-113.4  (MLP immaterial)
//   128thr/U4 float4:                    113.6        (2KB sweeps slightly worse)
//   256thr/U2 v8.f32 256-bit ops:        113.8        (fewer wavefronts ->
//                                         worse DRAM request interleave)
//   persistent 888-block grid:           120.8        (tail starvation)
//   copy-engine memcpy2D:                ~390         (row-segmented CE path)
// Residual ~15% vs spec is HBM controller R/W turnaround on a bidirectional
// stream — invariant under MLP, occupancy, access width, cache policy, and
// transport path. Not addressable from SASS. Hardware roofline reached;
// further edits have negative expected value against the characterized
// noise distribution.

static constexpr int T_Q     = 21;
static constexpr int ROWS    = 1536 * 21;          // 32256
static constexpr int HID_F4  = 3072 / 4;           // 768 float4 per row (hidden)
static constexpr int ROW_F4  = 800;                // float4 per output row
static constexpr int PAD_T   = 8;
static constexpr long long TOTAL_F4 = (long long)ROWS * ROW_F4;  // 25,804,800
static constexpr int THREADS = 256;
static constexpr int UNROLL  = 4;
// 25,804,800 / (256*4) = 25200 exactly -> predicate-free grid.
static constexpr int BLOCKS  = (int)(TOTAL_F4 / (THREADS * UNROLL));

__device__ __forceinline__ float4 fetch_one(const float4* __restrict__ hidden,
                                            const float4* __restrict__ vcc,
                                            int i)
{
    int row  = i / ROW_F4;          // compile-time-constant divide -> IMAD magic
    int col4 = i - row * ROW_F4;

    if (col4 < HID_F4) {
        // hidden_idx = row*768 + col4 = i - 32*row
        return __ldcs(&hidden[i - 32 * row]);   // streaming: read exactly once
    } else {
        int c4 = col4 - HID_F4;      // 0..31
        int p  = c4 >> 2;            // PAD_T slot (0..7)
        int q  = c4 & 3;             // float4 within 16-float channel row
        int t  = row % T_Q;          // compile-time-constant mod
        int j  = 4 * t + p;          // padded index 0..88
        int src = (j < PAD_T) ? 0 : (j - PAD_T);
        return __ldg(&vcc[src * 4 + q]);   // 5KB table, L1-resident
    }
}

__global__ void __launch_bounds__(THREADS)
vcp_fuse_kernel(const float4* __restrict__ hidden,
                const float4* __restrict__ vcc,
                float4* __restrict__ out)
{
    // Block covers 1024 consecutive float4 (16KB dst span); each 256-thread
    // sweep is a contiguous, perfectly coalesced 4KB span. Warp spans never
    // straddle the hidden/tail boundary (768 and 800 are multiples of 32)
    // -> zero intra-warp divergence.
    int base = blockIdx.x * (THREADS * UNROLL) + threadIdx.x;

    float4 v[UNROLL];
    // Batch all loads first (per-thread MLP = 4), then all stores.
    #pragma unroll
    for (int u = 0; u < UNROLL; u++) {
        v[u] = fetch_one(hidden, vcc, base + u * THREADS);
    }
    #pragma unroll
    for (int u = 0; u < UNROLL; u++) {
        __stcs(&out[base + u * THREADS], v[u]);   // streaming store: never re-read
    }
}

extern "C" void kernel_launch(void* const* d_in, const int* in_sizes, int n_in,
                              void* d_out, int out_size)
{
    const float4* hidden = (const float4*)d_in[0];
    const float4* vcc    = (const float4*)d_in[1];
    float4* out = (float4*)d_out;

    vcp_fuse_kernel<<<BLOCKS, THREADS>>>(hidden, vcc, out);
}